// round 3
// baseline (speedup 1.0000x reference)
#include <cuda_runtime.h>
#include <math.h>

#define WS   7
#define DISP 3
#define NHEADS 8
#define HD   32
#define BATCH 16
#define CH   256
#define HH   56
#define WW   56
#define WS2  49   // tokens per window
#define NWIN 8    // windows per side (56/7)

// Precomputed fused weight products (32x32 each)
__device__ float g_M[HD * HD];  // M = Wq^T @ Wk / sqrt(HD)
__device__ float g_P[HD * HD];  // P = Wv^T @ Wl^T

__global__ void precompute_kernel(const float* __restrict__ Wq,
                                  const float* __restrict__ Wk,
                                  const float* __restrict__ Wv,
                                  const float* __restrict__ Wl) {
    int i = threadIdx.x;          // 0..1023
    int c = i >> 5, d = i & 31;
    float m = 0.f, p = 0.f;
#pragma unroll
    for (int j = 0; j < 32; ++j) {
        m += Wq[j * 32 + c] * Wk[j * 32 + d];   // (Wq^T Wk)[c][d]
        p += Wv[j * 32 + c] * Wl[d * 32 + j];   // (Wv^T Wl^T)[c][d]
    }
    g_M[i] = m * 0.17677669529663687f;          // fold 1/sqrt(32)
    g_P[i] = p;
}

__global__ __launch_bounds__(128, 5)
void swca_kernel(const float* __restrict__ x, const float* __restrict__ skip,
                 const float* __restrict__ pe, float* __restrict__ out) {
    const int win   = blockIdx.x;   // 0..63
    const int head  = blockIdx.y;   // 0..7
    const int batch = blockIdx.z;   // 0..15
    const int nh = win >> 3, nw = win & 7;
    const int tid  = threadIdx.x;
    const int lane = tid & 31, warp = tid >> 5;

    __shared__ float xs[WS2 * 33];   // x window tile (head slice), padded
    __shared__ float ss[WS2 * 33];   // skip window tile
    __shared__ float qm[WS2 * 33];   // xs @ M
    __shared__ float vo[WS2 * 33];   // ss @ P  (v projected through Wl already)
    __shared__ float at[WS2 * 50];   // attention probs
    __shared__ float pes[169];       // 13x13 positional table
    __shared__ float Ms[1024];
    __shared__ float Ps[1024];
    __shared__ int   srow[WS2];      // row*56+col per token (after roll)

    for (int i = tid; i < 169; i += 128) pes[i] = pe[i];
    for (int i = tid; i < 1024; i += 128) { Ms[i] = g_M[i]; Ps[i] = g_P[i]; }
    if (tid < WS2) {
        int wi = tid / 7, wj = tid % 7;
        int r  = (nh * 7 + wi + DISP) % HH;   // roll by -DISP => source at +DISP
        int cc = (nw * 7 + wj + DISP) % WW;
        srow[tid] = r * WW + cc;
    }
    __syncthreads();

    const size_t base = (size_t)batch * (HH * WW) * CH + head * HD;

    // Gather window tiles (coalesced 128B per token row)
    for (int idx = tid; idx < WS2 * HD; idx += 128) {
        int t = idx >> 5, c = idx & 31;
        size_t g = base + (size_t)srow[t] * CH + c;
        xs[t * 33 + c] = x[g];
        ss[t * 33 + c] = skip[g];
    }
    __syncthreads();

    // Projections: qm = xs @ M, vo = ss @ P. Lane d is fixed => keep M column in regs.
    {
        float mreg[32];
#pragma unroll
        for (int c = 0; c < 32; ++c) mreg[c] = Ms[c * 32 + lane];
        for (int t = warp; t < WS2; t += 4) {
            float acc = 0.f;
#pragma unroll
            for (int c = 0; c < 32; ++c) acc += xs[t * 33 + c] * mreg[c];
            qm[t * 33 + lane] = acc;
        }
#pragma unroll
        for (int c = 0; c < 32; ++c) mreg[c] = Ps[c * 32 + lane];
        for (int t = warp; t < WS2; t += 4) {
            float acc = 0.f;
#pragma unroll
            for (int c = 0; c < 32; ++c) acc += ss[t * 33 + c] * mreg[c];
            vo[t * 33 + lane] = acc;
        }
    }
    __syncthreads();

    // Scores + bias + shift-masks + softmax. Warp per query token; lane covers 2 keys.
    const bool mrow = (nh == 7);
    const bool mcol = (nw == 7);
    const float NEGINF = __int_as_float(0xff800000u);
    for (int qt = warp; qt < WS2; qt += 4) {
        int qi = qt / 7, qj = qt % 7;
        int kt1 = lane;
        int kt2 = lane + 32;
        int kt2c = (kt2 < WS2) ? kt2 : 0;
        float a1 = 0.f, a2 = 0.f;
#pragma unroll
        for (int d = 0; d < 32; ++d) {
            float qv = qm[qt * 33 + d];           // broadcast
            a1 += qv * xs[kt1 * 33 + d];          // conflict-free (pad 33)
            a2 += qv * xs[kt2c * 33 + d];
        }
        int k1i = kt1 / 7, k1j = kt1 % 7;
        float s1 = a1 + pes[(k1i - qi + 6) * 13 + (k1j - qj + 6)];
        if (mrow && ((qi >= 4) != (k1i >= 4))) s1 = NEGINF;
        if (mcol && ((qj >= 4) != (k1j >= 4))) s1 = NEGINF;
        float s2 = NEGINF;
        if (kt2 < WS2) {
            int k2i = kt2 / 7, k2j = kt2 % 7;
            s2 = a2 + pes[(k2i - qi + 6) * 13 + (k2j - qj + 6)];
            if (mrow && ((qi >= 4) != (k2i >= 4))) s2 = NEGINF;
            if (mcol && ((qj >= 4) != (k2j >= 4))) s2 = NEGINF;
        }
        float mx = fmaxf(s1, s2);
#pragma unroll
        for (int o = 16; o > 0; o >>= 1) mx = fmaxf(mx, __shfl_xor_sync(0xffffffffu, mx, o));
        float e1 = __expf(s1 - mx);
        float e2 = (kt2 < WS2) ? __expf(s2 - mx) : 0.f;
        float sm = e1 + e2;
#pragma unroll
        for (int o = 16; o > 0; o >>= 1) sm += __shfl_xor_sync(0xffffffffu, sm, o);
        float inv = 1.f / sm;
        at[qt * 50 + kt1] = e1 * inv;
        if (kt2 < WS2) at[qt * 50 + kt2] = e2 * inv;
    }
    __syncthreads();

    // out = attn @ vo ; write directly (vo already includes Wl^T)
    for (int qt = warp; qt < WS2; qt += 4) {
        float acc = 0.f;
#pragma unroll
        for (int kt = 0; kt < WS2; ++kt)
            acc += at[qt * 50 + kt] * vo[kt * 33 + lane];
        size_t g = base + (size_t)srow[qt] * CH + lane;
        out[g] = acc;
    }
}

extern "C" void kernel_launch(void* const* d_in, const int* in_sizes, int n_in,
                              void* d_out, int out_size) {
    const float* skip = (const float*)d_in[0];
    const float* x    = (const float*)d_in[1];
    const float* Wq   = (const float*)d_in[2];
    const float* Wk   = (const float*)d_in[3];
    const float* Wv   = (const float*)d_in[4];
    const float* Wl   = (const float*)d_in[5];
    const float* pe   = (const float*)d_in[6];
    (void)in_sizes; (void)n_in; (void)out_size;

    precompute_kernel<<<1, 1024>>>(Wq, Wk, Wv, Wl);
    dim3 grid(64, NHEADS, BATCH);
    swca_kernel<<<grid, 128>>>(x, skip, pe, (float*)d_out);
}

// round 4
// speedup vs baseline: 1.4004x; 1.4004x over previous
#include <cuda_runtime.h>
#include <math.h>

#define WS   7
#define DISP 3
#define NHEADS 8
#define HD   32
#define BATCH 16
#define CH   256
#define HH   56
#define WW   56
#define WS2  49   // tokens per window
#define PAD  36   // smem row pitch (floats): 16B-aligned, conflict-free for .128
#define ATP  52   // attention row pitch (floats): 16B-aligned

// Precomputed fused weight products (32x32 each)
__device__ float g_M[HD * HD];  // M = Wq^T @ Wk / sqrt(HD)
__device__ float g_P[HD * HD];  // P = Wv^T @ Wl^T

__global__ void precompute_kernel(const float* __restrict__ Wq,
                                  const float* __restrict__ Wk,
                                  const float* __restrict__ Wv,
                                  const float* __restrict__ Wl) {
    int i = threadIdx.x;          // 0..1023
    int c = i >> 5, d = i & 31;
    float m = 0.f, p = 0.f;
#pragma unroll
    for (int j = 0; j < 32; ++j) {
        m += Wq[j * 32 + c] * Wk[j * 32 + d];   // (Wq^T Wk)[c][d]
        p += Wv[j * 32 + c] * Wl[d * 32 + j];   // (Wv^T Wl^T)[c][d]
    }
    g_M[i] = m * 0.17677669529663687f;          // fold 1/sqrt(32)
    g_P[i] = p;
}

__global__ __launch_bounds__(128, 6)
void swca_kernel(const float* __restrict__ x, const float* __restrict__ skip,
                 const float* __restrict__ pe, float* __restrict__ out) {
    const int win   = blockIdx.x;   // 0..63
    const int head  = blockIdx.y;   // 0..7
    const int batch = blockIdx.z;   // 0..15
    const int nh = win >> 3, nw = win & 7;
    const int tid  = threadIdx.x;
    const int lane = tid & 31, warp = tid >> 5;

    __shared__ __align__(16) float xs[WS2 * PAD];   // x window tile (keys)
    __shared__ __align__(16) float ss[WS2 * PAD];   // skip tile, overwritten by vo in-place
    __shared__ __align__(16) float qm[WS2 * PAD];   // xs @ M
    __shared__ __align__(16) float at[WS2 * ATP];   // attention probs
    __shared__ float pes[169];                      // 13x13 positional table
    __shared__ int   srow[WS2];                     // row*56+col per token (after roll)

    for (int i = tid; i < 169; i += 128) pes[i] = pe[i];

    const size_t base = (size_t)batch * (HH * WW) * CH + head * HD;

    // Gather window tiles with float4 loads; compute srow inline.
    for (int idx = tid; idx < WS2 * 8; idx += 128) {
        int t  = idx >> 3;
        int c4 = (idx & 7) << 2;
        int wi = t / 7, wj = t - wi * 7;
        int r  = nh * 7 + wi + DISP;  if (r  >= HH) r  -= HH;
        int cc = nw * 7 + wj + DISP;  if (cc >= WW) cc -= WW;
        int sr = r * WW + cc;
        if ((idx & 7) == 0) srow[t] = sr;
        size_t g = base + (size_t)sr * CH + c4;
        *(float4*)&xs[t * PAD + c4] = *(const float4*)(x + g);
        *(float4*)&ss[t * PAD + c4] = *(const float4*)(skip + g);
    }
    __syncthreads();

    // ---- Projections. Lane owns output dim d=lane; warp owns rows t = warp::4.
    {
        float mreg[32];
#pragma unroll
        for (int c = 0; c < 32; ++c) mreg[c] = g_M[c * 32 + lane];
        for (int t = warp; t < WS2; t += 4) {
            float acc = 0.f;
#pragma unroll
            for (int c4 = 0; c4 < 32; c4 += 4) {
                float4 xv = *(const float4*)&xs[t * PAD + c4];
                acc += xv.x * mreg[c4] + xv.y * mreg[c4 + 1]
                     + xv.z * mreg[c4 + 2] + xv.w * mreg[c4 + 3];
            }
            qm[t * PAD + lane] = acc;
        }
#pragma unroll
        for (int c = 0; c < 32; ++c) mreg[c] = g_P[c * 32 + lane];
        for (int t = warp; t < WS2; t += 4) {
            float acc = 0.f;
#pragma unroll
            for (int c4 = 0; c4 < 32; c4 += 4) {
                float4 xv = *(const float4*)&ss[t * PAD + c4];
                acc += xv.x * mreg[c4] + xv.y * mreg[c4 + 1]
                     + xv.z * mreg[c4 + 2] + xv.w * mreg[c4 + 3];
            }
            __syncwarp();                // all lanes done reading row t
            ss[t * PAD + lane] = acc;    // vo overwrites ss in-place (warp-private row)
        }
    }
    // No __syncthreads needed: scores read qm rows owned by this warp, xs is stable.

    // ---- Scores: lane owns keys kt1=lane, kt2=lane+32; 13 query accumulators.
    const bool mrow = (nh == 7);
    const bool mcol = (nw == 7);
    const float NEGINF = __int_as_float(0xff800000u);
    const int  kt1  = lane;
    const int  kt2  = lane + 32;
    const bool k2v  = (kt2 < WS2);
    const int  kt2c = k2v ? kt2 : 0;
    const int  k1i = kt1 / 7, k1j = kt1 - k1i * 7;
    const int  k2i = kt2c / 7, k2j = kt2c - k2i * 7;
    const bool k1ge_i = (k1i >= 4), k1ge_j = (k1j >= 4);
    const bool k2ge_i = (k2i >= 4), k2ge_j = (k2j >= 4);

    float a1[13], a2[13];
#pragma unroll
    for (int i = 0; i < 13; ++i) { a1[i] = 0.f; a2[i] = 0.f; }

#pragma unroll
    for (int c4 = 0; c4 < 32; c4 += 4) {
        float4 k1 = *(const float4*)&xs[kt1  * PAD + c4];
        float4 k2 = *(const float4*)&xs[kt2c * PAD + c4];
#pragma unroll
        for (int i = 0; i < 13; ++i) {
            int qt = warp + (i << 2);
            if (qt < WS2) {
                float4 q = *(const float4*)&qm[qt * PAD + c4];
                a1[i] += q.x * k1.x + q.y * k1.y + q.z * k1.z + q.w * k1.w;
                a2[i] += q.x * k2.x + q.y * k2.y + q.z * k2.z + q.w * k2.w;
            }
        }
    }

    // ---- Softmax per query (values live in regs across the warp's lanes).
#pragma unroll
    for (int i = 0; i < 13; ++i) {
        int qt = warp + (i << 2);
        if (qt < WS2) {
            int qi = qt / 7, qj = qt - qi * 7;
            bool qge_i = (qi >= 4), qge_j = (qj >= 4);
            float s1 = a1[i] + pes[(k1i - qi + 6) * 13 + (k1j - qj + 6)];
            if ((mrow && (qge_i != k1ge_i)) || (mcol && (qge_j != k1ge_j))) s1 = NEGINF;
            float s2 = NEGINF;
            if (k2v) {
                s2 = a2[i] + pes[(k2i - qi + 6) * 13 + (k2j - qj + 6)];
                if ((mrow && (qge_i != k2ge_i)) || (mcol && (qge_j != k2ge_j))) s2 = NEGINF;
            }
            float mx = fmaxf(s1, s2);
#pragma unroll
            for (int o = 16; o > 0; o >>= 1)
                mx = fmaxf(mx, __shfl_xor_sync(0xffffffffu, mx, o));
            float e1 = __expf(s1 - mx);
            float e2 = k2v ? __expf(s2 - mx) : 0.f;
            float sm = e1 + e2;
#pragma unroll
            for (int o = 16; o > 0; o >>= 1)
                sm += __shfl_xor_sync(0xffffffffu, sm, o);
            float inv = 1.f / sm;
            at[qt * ATP + kt1] = e1 * inv;
            if (k2v) at[qt * ATP + kt2] = e2 * inv;
        }
    }
    __syncthreads();   // vo (in ss) must be complete across warps; at is warp-private

    // ---- out = attn @ vo. Lane owns dim d=lane; v values loaded once per kt block.
    {
        float acc[13];
#pragma unroll
        for (int i = 0; i < 13; ++i) acc[i] = 0.f;

        for (int ktb = 0; ktb < 48; ktb += 4) {
            float v0 = ss[(ktb + 0) * PAD + lane];
            float v1 = ss[(ktb + 1) * PAD + lane];
            float v2 = ss[(ktb + 2) * PAD + lane];
            float v3 = ss[(ktb + 3) * PAD + lane];
#pragma unroll
            for (int i = 0; i < 13; ++i) {
                int qt = warp + (i << 2);
                if (qt < WS2) {
                    float4 a = *(const float4*)&at[qt * ATP + ktb];
                    acc[i] += a.x * v0 + a.y * v1 + a.z * v2 + a.w * v3;
                }
            }
        }
        {   // remainder kt = 48
            float v = ss[48 * PAD + lane];
#pragma unroll
            for (int i = 0; i < 13; ++i) {
                int qt = warp + (i << 2);
                if (qt < WS2) acc[i] += at[qt * ATP + 48] * v;
            }
        }
#pragma unroll
        for (int i = 0; i < 13; ++i) {
            int qt = warp + (i << 2);
            if (qt < WS2)
                out[base + (size_t)srow[qt] * CH + lane] = acc[i];
        }
    }
}

extern "C" void kernel_launch(void* const* d_in, const int* in_sizes, int n_in,
                              void* d_out, int out_size) {
    const float* skip = (const float*)d_in[0];
    const float* x    = (const float*)d_in[1];
    const float* Wq   = (const float*)d_in[2];
    const float* Wk   = (const float*)d_in[3];
    const float* Wv   = (const float*)d_in[4];
    const float* Wl   = (const float*)d_in[5];
    const float* pe   = (const float*)d_in[6];
    (void)in_sizes; (void)n_in; (void)out_size;

    precompute_kernel<<<1, 1024>>>(Wq, Wk, Wv, Wl);
    dim3 grid(64, NHEADS, BATCH);
    swca_kernel<<<grid, 128>>>(x, skip, pe, (float*)d_out);
}

// round 5
// speedup vs baseline: 2.2407x; 1.6000x over previous
#include <cuda_runtime.h>
#include <math.h>

#define DISP 3
#define CH   256
#define HH   56
#define WW   56
#define WS2  49
#define RP   36      // pitch for xs/ss/qm (floats)
#define AP   60      // pitch for at (floats)
#define MPP  36      // pitch for transposed M/P
#define VP   60      // pitch for transposed vo

// uni region offsets (floats). Phase A: qm@0, MsT@2304, PsT@3456 (ends 4608)
// Phase B: at@0 (3840), voT@3840 (32*60=1920, ends 5760)
#define QM_OFF 0
#define MS_OFF 2304
#define PS_OFF 3456
#define AT_OFF 0
#define VT_OFF 3840
#define UNI_SZ 5760

__device__ float g_M[1024];  // tf32-rounded  M = Wq^T Wk / sqrt(32)
__device__ float g_P[1024];  // tf32-rounded  P = Wv^T Wl^T

__device__ __forceinline__ float tf32r(float x) {
    unsigned u; asm("cvt.rna.tf32.f32 %0, %1;" : "=r"(u) : "f"(x));
    return __uint_as_float(u);
}

__device__ __forceinline__ void mma_tf32(float& c0, float& c1, float& c2, float& c3,
                                         unsigned a0, unsigned a1, unsigned a2, unsigned a3,
                                         unsigned b0, unsigned b1) {
    asm volatile("mma.sync.aligned.m16n8k8.row.col.f32.tf32.tf32.f32 "
        "{%0,%1,%2,%3}, {%4,%5,%6,%7}, {%8,%9}, {%0,%1,%2,%3};"
        : "+f"(c0), "+f"(c1), "+f"(c2), "+f"(c3)
        : "r"(a0), "r"(a1), "r"(a2), "r"(a3), "r"(b0), "r"(b1));
}

__global__ void precompute_kernel(const float* __restrict__ Wq,
                                  const float* __restrict__ Wk,
                                  const float* __restrict__ Wv,
                                  const float* __restrict__ Wl) {
    int i = threadIdx.x;          // 0..1023
    int c = i >> 5, d = i & 31;
    float m = 0.f, p = 0.f;
#pragma unroll
    for (int j = 0; j < 32; ++j) {
        m += Wq[j * 32 + c] * Wk[j * 32 + d];   // (Wq^T Wk)[c][d]
        p += Wv[j * 32 + c] * Wl[d * 32 + j];   // (Wv^T Wl^T)[c][d]
    }
    g_M[i] = tf32r(m * 0.17677669529663687f);
    g_P[i] = tf32r(p);
}

__global__ __launch_bounds__(128, 5)
void swca_kernel(const float* __restrict__ x, const float* __restrict__ skip,
                 const float* __restrict__ pe, float* __restrict__ out) {
    const int win   = blockIdx.x;   // 0..63
    const int head  = blockIdx.y;
    const int batch = blockIdx.z;
    const int nh = win >> 3, nw = win & 7;
    const int tid  = threadIdx.x;
    const int lane = tid & 31, warp = tid >> 5;
    const int lr = lane >> 2, lc = lane & 3;   // quad row / quad col
    const int m0 = warp * 16;                  // this warp's row-tile base

    __shared__ float xs[64 * RP];
    __shared__ float ss[64 * RP];    // skip tile (dead after vo proj)
    __shared__ float uni[UNI_SZ];
    __shared__ float pes[169];
    __shared__ int   srow[WS2];

    for (int i = tid; i < 169; i += 128) pes[i] = pe[i];
    for (int i = tid; i < 1024; i += 128) {
        // store TRANSPOSED: MsT[d][c] = M[c][d]
        uni[MS_OFF + (i & 31) * MPP + (i >> 5)] = g_M[i];
        uni[PS_OFF + (i & 31) * MPP + (i >> 5)] = g_P[i];
    }
    for (int i = 4608 + tid; i < UNI_SZ; i += 128) uni[i] = 0.f;  // voT tail zeros

    const size_t base = (size_t)batch * (HH * WW) * CH + head * 32;

    // ---- gather (rows 49..63 zero-padded), convert to tf32 once
    for (int idx = tid; idx < 64 * 8; idx += 128) {
        int t = idx >> 3, c4 = (idx & 7) << 2;
        float4 xv = make_float4(0.f, 0.f, 0.f, 0.f);
        float4 sv = xv;
        if (t < WS2) {
            int wi = t / 7, wj = t - wi * 7;
            int r  = nh * 7 + wi + DISP;  if (r  >= HH) r  -= HH;
            int cc = nw * 7 + wj + DISP;  if (cc >= WW) cc -= WW;
            int sr = r * WW + cc;
            if (c4 == 0) srow[t] = sr;
            size_t g = base + (size_t)sr * CH + c4;
            xv = *(const float4*)(x + g);
            sv = *(const float4*)(skip + g);
        }
        xv.x = tf32r(xv.x); xv.y = tf32r(xv.y); xv.z = tf32r(xv.z); xv.w = tf32r(xv.w);
        sv.x = tf32r(sv.x); sv.y = tf32r(sv.y); sv.z = tf32r(sv.z); sv.w = tf32r(sv.w);
        *(float4*)&xs[t * RP + c4] = xv;
        *(float4*)&ss[t * RP + c4] = sv;
    }
    __syncthreads();

    // ================= projections (tensor core) =================
    float vc[4][4];   // vo c-frags held in regs until after sync
    {
        unsigned a[4][4];
        // ---- qm = xs @ M
#pragma unroll
        for (int kt = 0; kt < 4; ++kt) {
            int k0 = kt * 8;
            a[kt][0] = __float_as_uint(xs[(m0 + lr)     * RP + k0 + lc]);
            a[kt][1] = __float_as_uint(xs[(m0 + lr + 8) * RP + k0 + lc]);
            a[kt][2] = __float_as_uint(xs[(m0 + lr)     * RP + k0 + lc + 4]);
            a[kt][3] = __float_as_uint(xs[(m0 + lr + 8) * RP + k0 + lc + 4]);
        }
#pragma unroll
        for (int nt = 0; nt < 4; ++nt) {
            float c0 = 0.f, c1 = 0.f, c2 = 0.f, c3 = 0.f;
#pragma unroll
            for (int kt = 0; kt < 4; ++kt) {
                unsigned b0 = __float_as_uint(uni[MS_OFF + (nt * 8 + lr) * MPP + kt * 8 + lc]);
                unsigned b1 = __float_as_uint(uni[MS_OFF + (nt * 8 + lr) * MPP + kt * 8 + lc + 4]);
                mma_tf32(c0, c1, c2, c3, a[kt][0], a[kt][1], a[kt][2], a[kt][3], b0, b1);
            }
            *(float2*)&uni[QM_OFF + (m0 + lr)     * RP + nt * 8 + 2 * lc] =
                make_float2(tf32r(c0), tf32r(c1));
            *(float2*)&uni[QM_OFF + (m0 + lr + 8) * RP + nt * 8 + 2 * lc] =
                make_float2(tf32r(c2), tf32r(c3));
        }
        // ---- vo = ss @ P (results kept in regs; stored transposed after sync)
#pragma unroll
        for (int kt = 0; kt < 4; ++kt) {
            int k0 = kt * 8;
            a[kt][0] = __float_as_uint(ss[(m0 + lr)     * RP + k0 + lc]);
            a[kt][1] = __float_as_uint(ss[(m0 + lr + 8) * RP + k0 + lc]);
            a[kt][2] = __float_as_uint(ss[(m0 + lr)     * RP + k0 + lc + 4]);
            a[kt][3] = __float_as_uint(ss[(m0 + lr + 8) * RP + k0 + lc + 4]);
        }
#pragma unroll
        for (int nt = 0; nt < 4; ++nt) {
            float c0 = 0.f, c1 = 0.f, c2 = 0.f, c3 = 0.f;
#pragma unroll
            for (int kt = 0; kt < 4; ++kt) {
                unsigned b0 = __float_as_uint(uni[PS_OFF + (nt * 8 + lr) * MPP + kt * 8 + lc]);
                unsigned b1 = __float_as_uint(uni[PS_OFF + (nt * 8 + lr) * MPP + kt * 8 + lc + 4]);
                mma_tf32(c0, c1, c2, c3, a[kt][0], a[kt][1], a[kt][2], a[kt][3], b0, b1);
            }
            vc[nt][0] = c0; vc[nt][1] = c1; vc[nt][2] = c2; vc[nt][3] = c3;
        }
    }
    __syncthreads();   // qm complete everywhere; all Ms/Ps reads done

    // store voT[d][token] (overlays Ps region + zeroed tail); tokens 56..63 skipped
    {
        int r0 = m0 + lr, r1 = r0 + 8;
#pragma unroll
        for (int nt = 0; nt < 4; ++nt) {
            int d0 = nt * 8 + 2 * lc;
            uni[VT_OFF + d0       * VP + r0] = tf32r(vc[nt][0]);
            uni[VT_OFF + (d0 + 1) * VP + r0] = tf32r(vc[nt][1]);
            if (r1 < 56) {
                uni[VT_OFF + d0       * VP + r1] = tf32r(vc[nt][2]);
                uni[VT_OFF + (d0 + 1) * VP + r1] = tf32r(vc[nt][3]);
            }
        }
    }

    // ================= scores = qm @ xs^T =================
    float sc[7][4];
    {
        unsigned qa[4][4];
#pragma unroll
        for (int kt = 0; kt < 4; ++kt) {
            int k0 = kt * 8;
            qa[kt][0] = __float_as_uint(uni[QM_OFF + (m0 + lr)     * RP + k0 + lc]);
            qa[kt][1] = __float_as_uint(uni[QM_OFF + (m0 + lr + 8) * RP + k0 + lc]);
            qa[kt][2] = __float_as_uint(uni[QM_OFF + (m0 + lr)     * RP + k0 + lc + 4]);
            qa[kt][3] = __float_as_uint(uni[QM_OFF + (m0 + lr + 8) * RP + k0 + lc + 4]);
        }
#pragma unroll
        for (int nt = 0; nt < 7; ++nt) {
            float c0 = 0.f, c1 = 0.f, c2 = 0.f, c3 = 0.f;
#pragma unroll
            for (int kt = 0; kt < 4; ++kt) {
                unsigned b0 = __float_as_uint(xs[(nt * 8 + lr) * RP + kt * 8 + lc]);
                unsigned b1 = __float_as_uint(xs[(nt * 8 + lr) * RP + kt * 8 + lc + 4]);
                mma_tf32(c0, c1, c2, c3, qa[kt][0], qa[kt][1], qa[kt][2], qa[kt][3], b0, b1);
            }
            sc[nt][0] = c0; sc[nt][1] = c1; sc[nt][2] = c2; sc[nt][3] = c3;
        }
    }
    __syncthreads();   // all qm reads done; union@0 becomes 'at'

    // ================= bias + mask + softmax (register resident) =================
    const bool mrow = (nh == 7), mcol = (nw == 7);
    const float NEG = -1e30f;
    const int r0 = m0 + lr, r1 = r0 + 8;
    {
        int rq0 = r0 < 49 ? r0 : 48, rq1 = r1 < 49 ? r1 : 48;
        int qi0 = rq0 / 7, qj0 = rq0 - qi0 * 7;
        int qi1 = rq1 / 7, qj1 = rq1 - qi1 * 7;
        int qo0 = (6 - qi0) * 13 + (6 - qj0);
        int qo1 = (6 - qi1) * 13 + (6 - qj1);
        bool q0i = qi0 >= 4, q0j = qj0 >= 4, q1i = qi1 >= 4, q1j = qj1 >= 4;

        float mx0 = NEG, mx1 = NEG;
#pragma unroll
        for (int nt = 0; nt < 7; ++nt) {
#pragma unroll
            for (int j = 0; j < 2; ++j) {
                int col = nt * 8 + 2 * lc + j;
                bool valid = col < 49;
                int colc = valid ? col : 0;
                int ki = colc / 7, kj = colc - ki * 7;
                int kidx = ki * 13 + kj;
                bool ki4 = ki >= 4, kj4 = kj >= 4;
                bool dead0 = !valid || (mrow && (ki4 != q0i)) || (mcol && (kj4 != q0j));
                bool dead1 = !valid || (mrow && (ki4 != q1i)) || (mcol && (kj4 != q1j));
                float s0 = dead0 ? NEG : sc[nt][j]     + pes[kidx + qo0];
                float s1 = dead1 ? NEG : sc[nt][2 + j] + pes[kidx + qo1];
                sc[nt][j] = s0; sc[nt][2 + j] = s1;
                mx0 = fmaxf(mx0, s0); mx1 = fmaxf(mx1, s1);
            }
        }
        mx0 = fmaxf(mx0, __shfl_xor_sync(0xffffffffu, mx0, 1));
        mx0 = fmaxf(mx0, __shfl_xor_sync(0xffffffffu, mx0, 2));
        mx1 = fmaxf(mx1, __shfl_xor_sync(0xffffffffu, mx1, 1));
        mx1 = fmaxf(mx1, __shfl_xor_sync(0xffffffffu, mx1, 2));
        float sm0 = 0.f, sm1 = 0.f;
#pragma unroll
        for (int nt = 0; nt < 7; ++nt) {
#pragma unroll
            for (int j = 0; j < 2; ++j) {
                float p0 = __expf(sc[nt][j]     - mx0);
                float p1 = __expf(sc[nt][2 + j] - mx1);
                sc[nt][j] = p0; sc[nt][2 + j] = p1;
                sm0 += p0; sm1 += p1;
            }
        }
        sm0 += __shfl_xor_sync(0xffffffffu, sm0, 1);
        sm0 += __shfl_xor_sync(0xffffffffu, sm0, 2);
        sm1 += __shfl_xor_sync(0xffffffffu, sm1, 1);
        sm1 += __shfl_xor_sync(0xffffffffu, sm1, 2);
        float inv0 = __fdividef(1.f, sm0), inv1 = __fdividef(1.f, sm1);
#pragma unroll
        for (int nt = 0; nt < 7; ++nt) {
            *(float2*)&uni[AT_OFF + r0 * AP + nt * 8 + 2 * lc] =
                make_float2(tf32r(sc[nt][0] * inv0), tf32r(sc[nt][1] * inv0));
            *(float2*)&uni[AT_OFF + r1 * AP + nt * 8 + 2 * lc] =
                make_float2(tf32r(sc[nt][2] * inv1), tf32r(sc[nt][3] * inv1));
        }
    }
    __syncthreads();

    // ================= out = at @ vo =================
    {
        unsigned aa[7][4];
#pragma unroll
        for (int kt = 0; kt < 7; ++kt) {
            int k0 = kt * 8;
            aa[kt][0] = __float_as_uint(uni[AT_OFF + r0 * AP + k0 + lc]);
            aa[kt][1] = __float_as_uint(uni[AT_OFF + r1 * AP + k0 + lc]);
            aa[kt][2] = __float_as_uint(uni[AT_OFF + r0 * AP + k0 + lc + 4]);
            aa[kt][3] = __float_as_uint(uni[AT_OFF + r1 * AP + k0 + lc + 4]);
        }
        bool w0 = r0 < WS2, w1 = r1 < WS2;
        size_t g0 = w0 ? base + (size_t)srow[r0] * CH : 0;
        size_t g1 = w1 ? base + (size_t)srow[r1] * CH : 0;
#pragma unroll
        for (int nt = 0; nt < 4; ++nt) {
            float c0 = 0.f, c1 = 0.f, c2 = 0.f, c3 = 0.f;
#pragma unroll
            for (int kt = 0; kt < 7; ++kt) {
                unsigned b0 = __float_as_uint(uni[VT_OFF + (nt * 8 + lr) * VP + kt * 8 + lc]);
                unsigned b1 = __float_as_uint(uni[VT_OFF + (nt * 8 + lr) * VP + kt * 8 + lc + 4]);
                mma_tf32(c0, c1, c2, c3, aa[kt][0], aa[kt][1], aa[kt][2], aa[kt][3], b0, b1);
            }
            int col = nt * 8 + 2 * lc;
            if (w0) *(float2*)(out + g0 + col) = make_float2(c0, c1);
            if (w1) *(float2*)(out + g1 + col) = make_float2(c2, c3);
        }
    }
}

extern "C" void kernel_launch(void* const* d_in, const int* in_sizes, int n_in,
                              void* d_out, int out_size) {
    const float* skip = (const float*)d_in[0];
    const float* x    = (const float*)d_in[1];
    const float* Wq   = (const float*)d_in[2];
    const float* Wk   = (const float*)d_in[3];
    const float* Wv   = (const float*)d_in[4];
    const float* Wl   = (const float*)d_in[5];
    const float* pe   = (const float*)d_in[6];
    (void)in_sizes; (void)n_in; (void)out_size;

    precompute_kernel<<<1, 1024>>>(Wq, Wk, Wv, Wl);
    dim3 grid(64, 8, 16);
    swca_kernel<<<grid, 128>>>(x, skip, pe, (float*)d_out);
}